// round 1
// baseline (speedup 1.0000x reference)
#include <cuda_runtime.h>
#include <cstdint>

#define T_ 4
#define B_ 32
#define C_ 512
#define N_ 256
#define H_ 8
#define D_ 64
#define BCN_ (B_*C_*N_)        // 4,194,304
#define TBCN_ (T_*BCN_)        // 16,777,216

// ---- scratch (device globals: allocation-free per harness rules) ----
__device__ float g_xs[TBCN_];
__device__ float g_q[TBCN_];
__device__ float g_k[TBCN_];
__device__ float g_v[TBCN_];
__device__ float g_kv[T_*B_*H_*D_*D_];   // 4,194,304
__device__ float g_s[TBCN_];

struct QKVArgs {
    const float* w[3];
    const float* gm[3];
    const float* bt[3];
    const float* mu[3];
    const float* var[3];
};

// LIF step exactly mirroring reference rounding: v = v + (x - v)/2; s = (v - vth >= 0); hard reset.
__device__ __forceinline__ float lif_step(float& v, float x, float vth) {
    v += (x - v) * 0.5f;
    float s = (v >= vth) ? 1.0f : 0.0f;
    if (s != 0.0f) v = 0.0f;
    return s;
}

#define FMA16(A, a4, b4) do { \
    A[0][0] += (a4).x*(b4).x; A[0][1] += (a4).x*(b4).y; A[0][2] += (a4).x*(b4).z; A[0][3] += (a4).x*(b4).w; \
    A[1][0] += (a4).y*(b4).x; A[1][1] += (a4).y*(b4).y; A[1][2] += (a4).y*(b4).z; A[1][3] += (a4).y*(b4).w; \
    A[2][0] += (a4).z*(b4).x; A[2][1] += (a4).z*(b4).y; A[2][2] += (a4).z*(b4).z; A[2][3] += (a4).z*(b4).w; \
    A[3][0] += (a4).w*(b4).x; A[3][1] += (a4).w*(b4).y; A[3][2] += (a4).w*(b4).z; A[3][3] += (a4).w*(b4).w; \
} while (0)

// ============================================================
// K1: proj_lif on x -> binary xs.  One thread = 4 (b,c,n) elems.
// ============================================================
__global__ void lif_x_kernel(const float* __restrict__ x) {
    int i = blockIdx.x * blockDim.x + threadIdx.x;   // over BCN_/4
    const float4* x4 = (const float4*)x;
    float4* o4 = (float4*)g_xs;
    float vx = 0.f, vy = 0.f, vz = 0.f, vw = 0.f;
    #pragma unroll
    for (int t = 0; t < T_; t++) {
        float4 xv = x4[(size_t)t * (BCN_/4) + i];
        float4 s;
        s.x = lif_step(vx, xv.x, 1.0f);
        s.y = lif_step(vy, xv.y, 1.0f);
        s.z = lif_step(vz, xv.z, 1.0f);
        s.w = lif_step(vw, xv.w, 1.0f);
        o4[(size_t)t * (BCN_/4) + i] = s;
    }
}

// ============================================================
// K2: q/k/v branch: Y = W @ xs per (t,b), BN, LIF over T.
// grid.x = 4(ntile) * 8(otile) * 32(b) = 1024, grid.y = branch.
// Block 256 thr, 64x64 tile, all 4 timesteps accumulated together.
// ============================================================
__global__ __launch_bounds__(256) void qkv_kernel(QKVArgs args) {
    __shared__ float  Ws[32][68];        // [k][o] transposed, padded
    __shared__ float4 Xs[T_][32][16];    // [t][k][n4]

    int br = blockIdx.y;
    int bx = blockIdx.x;
    int ntile = bx & 3, otile = (bx >> 2) & 7, b = bx >> 5;
    int tid = threadIdx.x;
    int ty = tid >> 4, tx = tid & 15;
    int oB = otile * 64, nB = ntile * 64;
    const float* __restrict__ W = args.w[br];

    float acc[T_][4][4];
    #pragma unroll
    for (int t = 0; t < T_; t++)
        #pragma unroll
        for (int i = 0; i < 4; i++)
            #pragma unroll
            for (int j = 0; j < 4; j++) acc[t][i][j] = 0.f;

    for (int kc = 0; kc < C_; kc += 32) {
        #pragma unroll
        for (int r = 0; r < 2; r++) {              // W tile: 64o x 32k = 512 float4
            int i = tid + r * 256;
            int o = i >> 3, kq = i & 7;
            float4 wv = *(const float4*)(W + (size_t)(oB + o) * C_ + kc + kq * 4);
            Ws[kq*4+0][o] = wv.x; Ws[kq*4+1][o] = wv.y;
            Ws[kq*4+2][o] = wv.z; Ws[kq*4+3][o] = wv.w;
        }
        #pragma unroll
        for (int r = 0; r < 8; r++) {              // X tiles: 4t x 32k x 64n = 2048 float4
            int i = tid + r * 256;
            int t = i >> 9, rem = i & 511, k = rem >> 4, n4 = rem & 15;
            Xs[t][k][n4] = *(const float4*)(g_xs +
                ((size_t)(t * B_ + b) * C_ + (kc + k)) * N_ + nB + n4 * 4);
        }
        __syncthreads();
        #pragma unroll 4
        for (int k = 0; k < 32; k++) {
            float4 a4 = *(const float4*)(&Ws[k][ty * 4]);
            #pragma unroll
            for (int t = 0; t < T_; t++) {
                float4 b4 = Xs[t][k][tx];
                FMA16(acc[t], a4, b4);
            }
        }
        __syncthreads();
    }

    // BN params per output row (mirror reference: (y - m) * (g / sqrt(v+eps)) + b)
    float scl[4], mean[4], beta[4];
    #pragma unroll
    for (int i = 0; i < 4; i++) {
        int o = oB + ty * 4 + i;
        scl[i]  = args.gm[br][o] / sqrtf(args.var[br][o] + 1e-5f);
        mean[i] = args.mu[br][o];
        beta[i] = args.bt[br][o];
    }
    float* outp = (br == 0) ? g_q : (br == 1) ? g_k : g_v;

    float vm[4][4];
    #pragma unroll
    for (int i = 0; i < 4; i++)
        #pragma unroll
        for (int j = 0; j < 4; j++) vm[i][j] = 0.f;

    #pragma unroll
    for (int t = 0; t < T_; t++) {
        #pragma unroll
        for (int i = 0; i < 4; i++) {
            float4 sp;
            float y;
            y = (acc[t][i][0] - mean[i]) * scl[i] + beta[i]; sp.x = lif_step(vm[i][0], y, 1.0f);
            y = (acc[t][i][1] - mean[i]) * scl[i] + beta[i]; sp.y = lif_step(vm[i][1], y, 1.0f);
            y = (acc[t][i][2] - mean[i]) * scl[i] + beta[i]; sp.z = lif_step(vm[i][2], y, 1.0f);
            y = (acc[t][i][3] - mean[i]) * scl[i] + beta[i]; sp.w = lif_step(vm[i][3], y, 1.0f);
            *(float4*)(outp + ((size_t)(t * B_ + b) * C_ + oB + ty * 4 + i) * N_ + nB + tx * 4) = sp;
        }
    }
}

// ============================================================
// K3a: kv[d,e] = sum_n k[n,d] * v[n,e] per (t,b,h).  1024 blocks.
// ============================================================
__global__ __launch_bounds__(256) void kv_kernel() {
    __shared__ float Ks[64][68];   // [n][d] transposed
    __shared__ float Vs[64][68];   // [n][e] transposed

    int tbh = blockIdx.x;                  // ((t*B+b)*H + h)
    int tb = tbh >> 3, hh = tbh & 7;
    size_t base = ((size_t)tb * C_ + hh * D_) * N_;
    int tid = threadIdx.x, ty = tid >> 4, tx = tid & 15;

    float acc[4][4];
    #pragma unroll
    for (int i = 0; i < 4; i++)
        #pragma unroll
        for (int j = 0; j < 4; j++) acc[i][j] = 0.f;

    for (int nc = 0; nc < N_; nc += 64) {
        #pragma unroll
        for (int r = 0; r < 4; r++) {
            int i = tid + r * 256;         // 0..1023 : 64d x 16 n4
            int dd = i >> 4, n4 = i & 15;
            float4 kq = *(const float4*)(g_k + base + (size_t)dd * N_ + nc + n4 * 4);
            Ks[n4*4+0][dd] = kq.x; Ks[n4*4+1][dd] = kq.y;
            Ks[n4*4+2][dd] = kq.z; Ks[n4*4+3][dd] = kq.w;
            float4 vq = *(const float4*)(g_v + base + (size_t)dd * N_ + nc + n4 * 4);
            Vs[n4*4+0][dd] = vq.x; Vs[n4*4+1][dd] = vq.y;
            Vs[n4*4+2][dd] = vq.z; Vs[n4*4+3][dd] = vq.w;
        }
        __syncthreads();
        #pragma unroll 4
        for (int n = 0; n < 64; n++) {
            float4 a4 = *(const float4*)(&Ks[n][ty * 4]);
            float4 b4 = *(const float4*)(&Vs[n][tx * 4]);
            FMA16(acc, a4, b4);
        }
        __syncthreads();
    }
    float* o = g_kv + (size_t)tbh * D_ * D_;
    #pragma unroll
    for (int i = 0; i < 4; i++) {
        float4 w4 = make_float4(acc[i][0], acc[i][1], acc[i][2], acc[i][3]);
        *(float4*)(o + (ty * 4 + i) * D_ + tx * 4) = w4;
    }
}

// ============================================================
// K3b: a = (q @ kv) * 0.125, LIF(0.5) over T, write attn spikes.
// grid = 4(ntile) * 8(h) * 32(b) = 1024 blocks; t looped inside.
// mapping: ty -> e (output channel), tx -> n (coalesced writes).
// ============================================================
__global__ __launch_bounds__(256) void attn_kernel() {
    __shared__ float4 Qs[64][16];    // [dd][n4]  (natural layout of g_q)
    __shared__ float4 KVs[64][16];   // [dd][e4]

    int bx = blockIdx.x;
    int ntile = bx & 3, hh = (bx >> 2) & 7, b = bx >> 5;
    int tid = threadIdx.x, ty = tid >> 4, tx = tid & 15;
    int nB = ntile * 64;

    float vm[4][4];
    #pragma unroll
    for (int i = 0; i < 4; i++)
        #pragma unroll
        for (int j = 0; j < 4; j++) vm[i][j] = 0.f;

    for (int t = 0; t < T_; t++) {
        int tb = t * B_ + b;
        #pragma unroll
        for (int r = 0; r < 4; r++) {
            int i = tid + r * 256;
            int dd = i >> 4, q4 = i & 15;
            Qs[dd][q4]  = *(const float4*)(g_q + ((size_t)tb * C_ + hh * D_ + dd) * N_ + nB + q4 * 4);
            KVs[dd][q4] = *(const float4*)(g_kv + ((size_t)tb * H_ + hh) * D_ * D_ + (size_t)dd * D_ + q4 * 4);
        }
        __syncthreads();
        float acc[4][4];
        #pragma unroll
        for (int i = 0; i < 4; i++)
            #pragma unroll
            for (int j = 0; j < 4; j++) acc[i][j] = 0.f;
        #pragma unroll 4
        for (int dd = 0; dd < 64; dd++) {
            float4 a4 = KVs[dd][ty];   // e dim
            float4 b4 = Qs[dd][tx];    // n dim
            FMA16(acc, a4, b4);
        }
        #pragma unroll
        for (int i = 0; i < 4; i++) {
            float4 sp;
            sp.x = lif_step(vm[i][0], acc[i][0] * 0.125f, 0.5f);
            sp.y = lif_step(vm[i][1], acc[i][1] * 0.125f, 0.5f);
            sp.z = lif_step(vm[i][2], acc[i][2] * 0.125f, 0.5f);
            sp.w = lif_step(vm[i][3], acc[i][3] * 0.125f, 0.5f);
            *(float4*)(g_s + ((size_t)tb * C_ + hh * D_ + ty * 4 + i) * N_ + nB + tx * 4) = sp;
        }
        __syncthreads();
    }
}

// ============================================================
// K4: y = BN(p_w @ s + bias).  grid = 4 * 8 * 128(tb) = 4096 blocks.
// ============================================================
__global__ __launch_bounds__(256) void proj_kernel(
    const float* __restrict__ pw, const float* __restrict__ pbias,
    const float* __restrict__ pg, const float* __restrict__ pb,
    const float* __restrict__ pm, const float* __restrict__ pv,
    float* __restrict__ out)
{
    __shared__ float  Ws[32][68];
    __shared__ float4 Ss[32][16];

    int bx = blockIdx.x;
    int ntile = bx & 3, otile = (bx >> 2) & 7, tb = bx >> 5;   // tb in [0,128)
    int tid = threadIdx.x, ty = tid >> 4, tx = tid & 15;
    int oB = otile * 64, nB = ntile * 64;

    float acc[4][4];
    #pragma unroll
    for (int i = 0; i < 4; i++)
        #pragma unroll
        for (int j = 0; j < 4; j++) acc[i][j] = 0.f;

    for (int kc = 0; kc < C_; kc += 32) {
        #pragma unroll
        for (int r = 0; r < 2; r++) {
            int i = tid + r * 256;
            int o = i >> 3, kq = i & 7;
            float4 wv = *(const float4*)(pw + (size_t)(oB + o) * C_ + kc + kq * 4);
            Ws[kq*4+0][o] = wv.x; Ws[kq*4+1][o] = wv.y;
            Ws[kq*4+2][o] = wv.z; Ws[kq*4+3][o] = wv.w;
        }
        #pragma unroll
        for (int r = 0; r < 2; r++) {
            int i = tid + r * 256;     // 32k x 16 n4 = 512 float4
            int k = i >> 4, n4 = i & 15;
            Ss[k][n4] = *(const float4*)(g_s + ((size_t)tb * C_ + kc + k) * N_ + nB + n4 * 4);
        }
        __syncthreads();
        #pragma unroll 4
        for (int k = 0; k < 32; k++) {
            float4 a4 = *(const float4*)(&Ws[k][ty * 4]);
            float4 b4 = Ss[k][tx];
            FMA16(acc, a4, b4);
        }
        __syncthreads();
    }

    #pragma unroll
    for (int i = 0; i < 4; i++) {
        int o = oB + ty * 4 + i;
        float scale = pg[o] / sqrtf(pv[o] + 1e-5f);
        float bias  = pbias[o], mu = pm[o], bb = pb[o];
        float4 w4;
        w4.x = ((acc[i][0] + bias) - mu) * scale + bb;
        w4.y = ((acc[i][1] + bias) - mu) * scale + bb;
        w4.z = ((acc[i][2] + bias) - mu) * scale + bb;
        w4.w = ((acc[i][3] + bias) - mu) * scale + bb;
        *(float4*)(out + ((size_t)tb * C_ + o) * N_ + nB + tx * 4) = w4;
    }
}

// ============================================================
extern "C" void kernel_launch(void* const* d_in, const int* in_sizes, int n_in,
                              void* d_out, int out_size) {
    (void)in_sizes; (void)n_in; (void)out_size;
    const float* x = (const float*)d_in[0];
    QKVArgs a;
    a.w[0]  = (const float*)d_in[1];  a.gm[0] = (const float*)d_in[2];
    a.bt[0] = (const float*)d_in[3];  a.mu[0] = (const float*)d_in[4];
    a.var[0]= (const float*)d_in[5];
    a.w[1]  = (const float*)d_in[6];  a.gm[1] = (const float*)d_in[7];
    a.bt[1] = (const float*)d_in[8];  a.mu[1] = (const float*)d_in[9];
    a.var[1]= (const float*)d_in[10];
    a.w[2]  = (const float*)d_in[11]; a.gm[2] = (const float*)d_in[12];
    a.bt[2] = (const float*)d_in[13]; a.mu[2] = (const float*)d_in[14];
    a.var[2]= (const float*)d_in[15];
    const float* pw    = (const float*)d_in[16];
    const float* pbias = (const float*)d_in[17];
    const float* pg    = (const float*)d_in[18];
    const float* pb    = (const float*)d_in[19];
    const float* pm    = (const float*)d_in[20];
    const float* pv    = (const float*)d_in[21];

    lif_x_kernel<<<BCN_ / 4 / 256, 256>>>(x);
    qkv_kernel<<<dim3(1024, 3, 1), 256>>>(a);
    kv_kernel<<<1024, 256>>>();
    attn_kernel<<<1024, 256>>>();
    proj_kernel<<<4096, 256>>>(pw, pbias, pg, pb, pm, pv, (float*)d_out);
}

// round 2
// speedup vs baseline: 1.0190x; 1.0190x over previous
#include <cuda_runtime.h>
#include <cstdint>

#define T_ 4
#define B_ 32
#define C_ 512
#define N_ 256
#define H_ 8
#define D_ 64
#define BCN_ (B_*C_*N_)        // 4,194,304
#define TBCN_ (T_*BCN_)        // 16,777,216

// ---- scratch (device globals: allocation-free per harness rules) ----
__device__ float g_xs[TBCN_];
__device__ float g_q[TBCN_];
__device__ float g_k[TBCN_];
__device__ float g_v[TBCN_];
__device__ float g_kv[T_*B_*H_*D_*D_];   // 4,194,304
__device__ float g_s[TBCN_];

typedef unsigned long long u64;

// packed fp32x2 FMA: two independent rn-rounded fp32 FMAs per issue slot.
__device__ __forceinline__ void fma2(u64 &d, u64 a, u64 b) {
    asm("fma.rn.f32x2 %0, %1, %2, %0;" : "+l"(d) : "l"(a), "l"(b));
}
__device__ __forceinline__ u64 pack2(float x, float y) {
    u64 r; asm("mov.b64 %0, {%1, %2};" : "=l"(r) : "f"(x), "f"(y)); return r;
}
__device__ __forceinline__ float2 unpack2(u64 v) {
    float2 f; asm("mov.b64 {%0, %1}, %2;" : "=f"(f.x), "=f"(f.y) : "l"(v)); return f;
}

struct QKVArgs {
    const float* w[3];
    const float* gm[3];
    const float* bt[3];
    const float* mu[3];
    const float* var[3];
};

// LIF step exactly mirroring reference rounding: v = v + (x - v)/2; s = (v - vth >= 0); hard reset.
__device__ __forceinline__ float lif_step(float& v, float x, float vth) {
    v += (x - v) * 0.5f;
    float s = (v >= vth) ? 1.0f : 0.0f;
    if (s != 0.0f) v = 0.0f;
    return s;
}

// 4x4 outer-product micro-tile via 8 packed FMA2s.
// A: u64[4][2] accumulators (rows i, col-pairs {0,1},{2,3})
#define FMA16_P(A, pa0, pa1, pa2, pa3, b01, b23) do { \
    fma2(A[0][0], pa0, b01); fma2(A[0][1], pa0, b23); \
    fma2(A[1][0], pa1, b01); fma2(A[1][1], pa1, b23); \
    fma2(A[2][0], pa2, b01); fma2(A[2][1], pa2, b23); \
    fma2(A[3][0], pa3, b01); fma2(A[3][1], pa3, b23); \
} while (0)

// ============================================================
// K1: proj_lif on x -> binary xs.  One thread = 4 (b,c,n) elems.
// ============================================================
__global__ void lif_x_kernel(const float* __restrict__ x) {
    int i = blockIdx.x * blockDim.x + threadIdx.x;   // over BCN_/4
    const float4* x4 = (const float4*)x;
    float4* o4 = (float4*)g_xs;
    float vx = 0.f, vy = 0.f, vz = 0.f, vw = 0.f;
    #pragma unroll
    for (int t = 0; t < T_; t++) {
        float4 xv = x4[(size_t)t * (BCN_/4) + i];
        float4 s;
        s.x = lif_step(vx, xv.x, 1.0f);
        s.y = lif_step(vy, xv.y, 1.0f);
        s.z = lif_step(vz, xv.z, 1.0f);
        s.w = lif_step(vw, xv.w, 1.0f);
        o4[(size_t)t * (BCN_/4) + i] = s;
    }
}

// ============================================================
// K2: q/k/v branch: Y = W @ xs per (t,b), BN, LIF over T.
// grid.x = 4(ntile) * 8(otile) * 32(b) = 1024, grid.y = branch.
// Block 256 thr, 64x64 tile, all 4 timesteps accumulated together.
// ============================================================
__global__ __launch_bounds__(256) void qkv_kernel(QKVArgs args) {
    __shared__ float  Ws[32][68];        // [k][o] transposed, padded
    __shared__ float4 Xs[T_][32][16];    // [t][k][n4]

    int br = blockIdx.y;
    int bx = blockIdx.x;
    int ntile = bx & 3, otile = (bx >> 2) & 7, b = bx >> 5;
    int tid = threadIdx.x;
    int ty = tid >> 4, tx = tid & 15;
    int oB = otile * 64, nB = ntile * 64;
    const float* __restrict__ W = args.w[br];

    u64 acc[T_][4][2];
    #pragma unroll
    for (int t = 0; t < T_; t++)
        #pragma unroll
        for (int i = 0; i < 4; i++) { acc[t][i][0] = 0ull; acc[t][i][1] = 0ull; }

    for (int kc = 0; kc < C_; kc += 32) {
        #pragma unroll
        for (int r = 0; r < 2; r++) {              // W tile: 64o x 32k = 512 float4
            int i = tid + r * 256;
            int o = i >> 3, kq = i & 7;
            float4 wv = *(const float4*)(W + (size_t)(oB + o) * C_ + kc + kq * 4);
            Ws[kq*4+0][o] = wv.x; Ws[kq*4+1][o] = wv.y;
            Ws[kq*4+2][o] = wv.z; Ws[kq*4+3][o] = wv.w;
        }
        #pragma unroll
        for (int r = 0; r < 8; r++) {              // X tiles: 4t x 32k x 64n = 2048 float4
            int i = tid + r * 256;
            int t = i >> 9, rem = i & 511, k = rem >> 4, n4 = rem & 15;
            Xs[t][k][n4] = *(const float4*)(g_xs +
                ((size_t)(t * B_ + b) * C_ + (kc + k)) * N_ + nB + n4 * 4);
        }
        __syncthreads();
        #pragma unroll 4
        for (int k = 0; k < 32; k++) {
            float4 a4 = *(const float4*)(&Ws[k][ty * 4]);
            u64 pa0 = pack2(a4.x, a4.x), pa1 = pack2(a4.y, a4.y);
            u64 pa2 = pack2(a4.z, a4.z), pa3 = pack2(a4.w, a4.w);
            #pragma unroll
            for (int t = 0; t < T_; t++) {
                float4 b4 = Xs[t][k][tx];
                u64 b01 = pack2(b4.x, b4.y), b23 = pack2(b4.z, b4.w);
                FMA16_P(acc[t], pa0, pa1, pa2, pa3, b01, b23);
            }
        }
        __syncthreads();
    }

    // BN params per output row (mirror reference: (y - m) * (g / sqrt(v+eps)) + b)
    float scl[4], mean[4], beta[4];
    #pragma unroll
    for (int i = 0; i < 4; i++) {
        int o = oB + ty * 4 + i;
        scl[i]  = args.gm[br][o] / sqrtf(args.var[br][o] + 1e-5f);
        mean[i] = args.mu[br][o];
        beta[i] = args.bt[br][o];
    }
    float* outp = (br == 0) ? g_q : (br == 1) ? g_k : g_v;

    float vm[4][4];
    #pragma unroll
    for (int i = 0; i < 4; i++)
        #pragma unroll
        for (int j = 0; j < 4; j++) vm[i][j] = 0.f;

    #pragma unroll
    for (int t = 0; t < T_; t++) {
        #pragma unroll
        for (int i = 0; i < 4; i++) {
            float2 c01 = unpack2(acc[t][i][0]);
            float2 c23 = unpack2(acc[t][i][1]);
            float4 sp;
            float y;
            y = (c01.x - mean[i]) * scl[i] + beta[i]; sp.x = lif_step(vm[i][0], y, 1.0f);
            y = (c01.y - mean[i]) * scl[i] + beta[i]; sp.y = lif_step(vm[i][1], y, 1.0f);
            y = (c23.x - mean[i]) * scl[i] + beta[i]; sp.z = lif_step(vm[i][2], y, 1.0f);
            y = (c23.y - mean[i]) * scl[i] + beta[i]; sp.w = lif_step(vm[i][3], y, 1.0f);
            *(float4*)(outp + ((size_t)(t * B_ + b) * C_ + oB + ty * 4 + i) * N_ + nB + tx * 4) = sp;
        }
    }
}

// ============================================================
// K3a: kv[d,e] = sum_n k[n,d] * v[n,e] per (t,b,h).  1024 blocks.
// ============================================================
__global__ __launch_bounds__(256) void kv_kernel() {
    __shared__ float Ks[64][68];   // [n][d] transposed
    __shared__ float Vs[64][68];   // [n][e] transposed

    int tbh = blockIdx.x;                  // ((t*B+b)*H + h)
    int tb = tbh >> 3, hh = tbh & 7;
    size_t base = ((size_t)tb * C_ + hh * D_) * N_;
    int tid = threadIdx.x, ty = tid >> 4, tx = tid & 15;

    u64 acc[4][2];
    #pragma unroll
    for (int i = 0; i < 4; i++) { acc[i][0] = 0ull; acc[i][1] = 0ull; }

    for (int nc = 0; nc < N_; nc += 64) {
        #pragma unroll
        for (int r = 0; r < 4; r++) {
            int i = tid + r * 256;         // 0..1023 : 64d x 16 n4
            int dd = i >> 4, n4 = i & 15;
            float4 kq = *(const float4*)(g_k + base + (size_t)dd * N_ + nc + n4 * 4);
            Ks[n4*4+0][dd] = kq.x; Ks[n4*4+1][dd] = kq.y;
            Ks[n4*4+2][dd] = kq.z; Ks[n4*4+3][dd] = kq.w;
            float4 vq = *(const float4*)(g_v + base + (size_t)dd * N_ + nc + n4 * 4);
            Vs[n4*4+0][dd] = vq.x; Vs[n4*4+1][dd] = vq.y;
            Vs[n4*4+2][dd] = vq.z; Vs[n4*4+3][dd] = vq.w;
        }
        __syncthreads();
        #pragma unroll 4
        for (int n = 0; n < 64; n++) {
            float4 a4 = *(const float4*)(&Ks[n][ty * 4]);
            float4 b4 = *(const float4*)(&Vs[n][tx * 4]);
            u64 pa0 = pack2(a4.x, a4.x), pa1 = pack2(a4.y, a4.y);
            u64 pa2 = pack2(a4.z, a4.z), pa3 = pack2(a4.w, a4.w);
            u64 b01 = pack2(b4.x, b4.y), b23 = pack2(b4.z, b4.w);
            FMA16_P(acc, pa0, pa1, pa2, pa3, b01, b23);
        }
        __syncthreads();
    }
    float* o = g_kv + (size_t)tbh * D_ * D_;
    #pragma unroll
    for (int i = 0; i < 4; i++) {
        float2 c01 = unpack2(acc[i][0]);
        float2 c23 = unpack2(acc[i][1]);
        float4 w4 = make_float4(c01.x, c01.y, c23.x, c23.y);
        *(float4*)(o + (ty * 4 + i) * D_ + tx * 4) = w4;
    }
}

// ============================================================
// K3b: a = (q @ kv) * 0.125, LIF(0.5) over T, write attn spikes.
// grid = 4(ntile) * 8(h) * 32(b) = 1024 blocks; t looped inside.
// mapping: ty -> e (output channel), tx -> n (coalesced writes).
// ============================================================
__global__ __launch_bounds__(256) void attn_kernel() {
    __shared__ float4 Qs[64][16];    // [dd][n4]  (natural layout of g_q)
    __shared__ float4 KVs[64][16];   // [dd][e4]

    int bx = blockIdx.x;
    int ntile = bx & 3, hh = (bx >> 2) & 7, b = bx >> 5;
    int tid = threadIdx.x, ty = tid >> 4, tx = tid & 15;
    int nB = ntile * 64;

    float vm[4][4];
    #pragma unroll
    for (int i = 0; i < 4; i++)
        #pragma unroll
        for (int j = 0; j < 4; j++) vm[i][j] = 0.f;

    for (int t = 0; t < T_; t++) {
        int tb = t * B_ + b;
        #pragma unroll
        for (int r = 0; r < 4; r++) {
            int i = tid + r * 256;
            int dd = i >> 4, q4 = i & 15;
            Qs[dd][q4]  = *(const float4*)(g_q + ((size_t)tb * C_ + hh * D_ + dd) * N_ + nB + q4 * 4);
            KVs[dd][q4] = *(const float4*)(g_kv + ((size_t)tb * H_ + hh) * D_ * D_ + (size_t)dd * D_ + q4 * 4);
        }
        __syncthreads();
        u64 acc[4][2];
        #pragma unroll
        for (int i = 0; i < 4; i++) { acc[i][0] = 0ull; acc[i][1] = 0ull; }
        #pragma unroll 4
        for (int dd = 0; dd < 64; dd++) {
            float4 a4 = KVs[dd][ty];   // e dim
            float4 b4 = Qs[dd][tx];    // n dim
            u64 pa0 = pack2(a4.x, a4.x), pa1 = pack2(a4.y, a4.y);
            u64 pa2 = pack2(a4.z, a4.z), pa3 = pack2(a4.w, a4.w);
            u64 b01 = pack2(b4.x, b4.y), b23 = pack2(b4.z, b4.w);
            FMA16_P(acc, pa0, pa1, pa2, pa3, b01, b23);
        }
        #pragma unroll
        for (int i = 0; i < 4; i++) {
            float2 c01 = unpack2(acc[i][0]);
            float2 c23 = unpack2(acc[i][1]);
            float4 sp;
            sp.x = lif_step(vm[i][0], c01.x * 0.125f, 0.5f);
            sp.y = lif_step(vm[i][1], c01.y * 0.125f, 0.5f);
            sp.z = lif_step(vm[i][2], c23.x * 0.125f, 0.5f);
            sp.w = lif_step(vm[i][3], c23.y * 0.125f, 0.5f);
            *(float4*)(g_s + ((size_t)tb * C_ + hh * D_ + ty * 4 + i) * N_ + nB + tx * 4) = sp;
        }
        __syncthreads();
    }
}

// ============================================================
// K4: y = BN(p_w @ s + bias).  grid = 4 * 8 * 128(tb) = 4096 blocks.
// ============================================================
__global__ __launch_bounds__(256) void proj_kernel(
    const float* __restrict__ pw, const float* __restrict__ pbias,
    const float* __restrict__ pg, const float* __restrict__ pb,
    const float* __restrict__ pm, const float* __restrict__ pv,
    float* __restrict__ out)
{
    __shared__ float  Ws[32][68];
    __shared__ float4 Ss[32][16];

    int bx = blockIdx.x;
    int ntile = bx & 3, otile = (bx >> 2) & 7, tb = bx >> 5;   // tb in [0,128)
    int tid = threadIdx.x, ty = tid >> 4, tx = tid & 15;
    int oB = otile * 64, nB = ntile * 64;

    u64 acc[4][2];
    #pragma unroll
    for (int i = 0; i < 4; i++) { acc[i][0] = 0ull; acc[i][1] = 0ull; }

    for (int kc = 0; kc < C_; kc += 32) {
        #pragma unroll
        for (int r = 0; r < 2; r++) {
            int i = tid + r * 256;
            int o = i >> 3, kq = i & 7;
            float4 wv = *(const float4*)(pw + (size_t)(oB + o) * C_ + kc + kq * 4);
            Ws[kq*4+0][o] = wv.x; Ws[kq*4+1][o] = wv.y;
            Ws[kq*4+2][o] = wv.z; Ws[kq*4+3][o] = wv.w;
        }
        #pragma unroll
        for (int r = 0; r < 2; r++) {
            int i = tid + r * 256;     // 32k x 16 n4 = 512 float4
            int k = i >> 4, n4 = i & 15;
            Ss[k][n4] = *(const float4*)(g_s + ((size_t)tb * C_ + kc + k) * N_ + nB + n4 * 4);
        }
        __syncthreads();
        #pragma unroll 4
        for (int k = 0; k < 32; k++) {
            float4 a4 = *(const float4*)(&Ws[k][ty * 4]);
            float4 b4 = Ss[k][tx];
            u64 pa0 = pack2(a4.x, a4.x), pa1 = pack2(a4.y, a4.y);
            u64 pa2 = pack2(a4.z, a4.z), pa3 = pack2(a4.w, a4.w);
            u64 b01 = pack2(b4.x, b4.y), b23 = pack2(b4.z, b4.w);
            FMA16_P(acc, pa0, pa1, pa2, pa3, b01, b23);
        }
        __syncthreads();
    }

    #pragma unroll
    for (int i = 0; i < 4; i++) {
        int o = oB + ty * 4 + i;
        float scale = pg[o] / sqrtf(pv[o] + 1e-5f);
        float bias  = pbias[o], mu = pm[o], bb = pb[o];
        float2 c01 = unpack2(acc[i][0]);
        float2 c23 = unpack2(acc[i][1]);
        float4 w4;
        w4.x = ((c01.x + bias) - mu) * scale + bb;
        w4.y = ((c01.y + bias) - mu) * scale + bb;
        w4.z = ((c23.x + bias) - mu) * scale + bb;
        w4.w = ((c23.y + bias) - mu) * scale + bb;
        *(float4*)(out + ((size_t)tb * C_ + o) * N_ + nB + tx * 4) = w4;
    }
}

// ============================================================
extern "C" void kernel_launch(void* const* d_in, const int* in_sizes, int n_in,
                              void* d_out, int out_size) {
    (void)in_sizes; (void)n_in; (void)out_size;
    const float* x = (const float*)d_in[0];
    QKVArgs a;
    a.w[0]  = (const float*)d_in[1];  a.gm[0] = (const float*)d_in[2];
    a.bt[0] = (const float*)d_in[3];  a.mu[0] = (const float*)d_in[4];
    a.var[0]= (const float*)d_in[5];
    a.w[1]  = (const float*)d_in[6];  a.gm[1] = (const float*)d_in[7];
    a.bt[1] = (const float*)d_in[8];  a.mu[1] = (const float*)d_in[9];
    a.var[1]= (const float*)d_in[10];
    a.w[2]  = (const float*)d_in[11]; a.gm[2] = (const float*)d_in[12];
    a.bt[2] = (const float*)d_in[13]; a.mu[2] = (const float*)d_in[14];
    a.var[2]= (const float*)d_in[15];
    const float* pw    = (const float*)d_in[16];
    const float* pbias = (const float*)d_in[17];
    const float* pg    = (const float*)d_in[18];
    const float* pb    = (const float*)d_in[19];
    const float* pm    = (const float*)d_in[20];
    const float* pv    = (const float*)d_in[21];

    lif_x_kernel<<<BCN_ / 4 / 256, 256>>>(x);
    qkv_kernel<<<dim3(1024, 3, 1), 256>>>(a);
    kv_kernel<<<1024, 256>>>();
    attn_kernel<<<1024, 256>>>();
    proj_kernel<<<4096, 256>>>(pw, pbias, pg, pb, pm, pv, (float*)d_out);
}